// round 5
// baseline (speedup 1.0000x reference)
#include <cuda_runtime.h>
#include <math.h>

#define H   4096
#define HS  64
#define NH  64
#define TM  64
#define TD  128
#define EPS 1e-5f
#define NBLK 592
#define NTHR 256

// ---------------- scratch ----------------
__device__ __align__(16) float g_xl[H];
__device__ __align__(16) float g_sx[H];
__device__ __align__(16) float g_mix[5 * H];
__device__ __align__(16) float g_r[H];
__device__ __align__(16) float g_k[H];
__device__ __align__(16) float g_v[H];
__device__ __align__(16) float g_g[H];
__device__ __align__(16) float g_og[H];
__device__ __align__(16) float g_ypart[32][5 * TM];   // P1 partials
__device__ __align__(16) float g_zpart[8][TD];        // decay1 partials
__device__ int g_barctr[8];                           // zero-init; reset each launch

__device__ __forceinline__ void grid_bar(int i) {
    __syncthreads();
    if (threadIdx.x == 0) {
        __threadfence();
        atomicAdd(&g_barctr[i], 1);
        while (*((volatile int*)&g_barctr[i]) < NBLK) __nanosleep(128);
        __threadfence();
    }
    __syncthreads();
}

__global__ void __launch_bounds__(NTHR, 4) mega(
        const float* __restrict__ x,      const float* __restrict__ state1,
        const float* __restrict__ state2, const float* __restrict__ ln1w,
        const float* __restrict__ ln1b,   const float* __restrict__ tmx,
        const float* __restrict__ tmaa,   const float* __restrict__ w1,
        const float* __restrict__ w2,     const float* __restrict__ tdec,
        const float* __restrict__ tfirst, const float* __restrict__ dw1,
        const float* __restrict__ dw2,    const float* __restrict__ Wr,
        const float* __restrict__ Wk,     const float* __restrict__ Wv,
        const float* __restrict__ Wg,     const float* __restrict__ Wo,
        const float* __restrict__ lnxw,   const float* __restrict__ lnxb,
        float* __restrict__ out) {
    __shared__ float sv[H];          // 16KB multi-purpose tile
    __shared__ float ssr[16];        // reduction scratch
    const int b = blockIdx.x, tid = threadIdx.x;
    const int warp = tid >> 5, lane = tid & 31;

    // ============ P0: LN + xm (blocks 0..31, each full, redundant) ============
    if (b < 32) {
        float vals[16];
        float s = 0.f, q = 0.f;
#pragma unroll
        for (int i = 0; i < 16; i++) {
            float v = x[tid + i * 256];
            vals[i] = v; s += v; q += v * v;
        }
        for (int o = 16; o; o >>= 1) { s += __shfl_down_sync(~0u, s, o); q += __shfl_down_sync(~0u, q, o); }
        if (lane == 0) { ssr[warp] = s; ssr[warp + 8] = q; }
        __syncthreads();
        if (tid < 8) {
            float a = ssr[tid], c = ssr[tid + 8];
            for (int o = 4; o; o >>= 1) { a += __shfl_down_sync(0xff, a, o); c += __shfl_down_sync(0xff, c, o); }
            if (tid == 0) { ssr[0] = a; ssr[8] = c; }
        }
        __syncthreads();
        float mu = ssr[0] * (1.f / H);
        float var = ssr[8] * (1.f / H) - mu * mu;
        float inv = rsqrtf(var + EPS);
#pragma unroll
        for (int i = 0; i < 16; i++) {
            int idx = tid + i * 256;
            float xl = (vals[i] - mu) * inv * ln1w[idx] + ln1b[idx];
            float sx = state1[idx] - xl;
            sv[idx] = xl + sx * tmx[idx];          // xm kept in smem
            if (b == 0) {
                g_xl[idx] = xl; g_sx[idx] = sx;
                out[H + idx] = xl;                 // output #2: xl
            }
        }
        __syncthreads();
        // ---- P1: y320 partials, 128 j-rows per block ----
        int j0 = b * 128;
        for (int c = tid; c < 320; c += 256) {
            float acc = 0.f;
#pragma unroll 8
            for (int j = 0; j < 128; j++)
                acc += sv[j0 + j] * w1[(j0 + j) * 320 + c];
            g_ypart[b][c] = acc;
        }
    }
    grid_bar(0);

    // ============ P2: mixes = xl + sx*(lora_up + time_maa) (blocks 0..79) ============
    if (b < 80) {
        int f = b >> 4;
        if (tid < TM) {
            float y = 0.f;
#pragma unroll
            for (int qq = 0; qq < 32; qq++) y += g_ypart[qq][f * TM + tid];
            sv[tid] = tanhf(y);                     // ty
        }
        __syncthreads();
        int gid = b * 256 + tid;
        int h = gid & (H - 1);
        const float* base = w2 + (size_t)f * TM * H + h;
        float acc = 0.f;
#pragma unroll
        for (int t = 0; t < TM; t++) acc += sv[t] * base[(size_t)t * H];
        g_mix[gid] = g_xl[h] + g_sx[h] * (acc + tmaa[gid]);
    }
    grid_bar(1);

    // ============ P3: 4 big GEMVs (584 blocks) + decay stage 1 (8 blocks) ============
    if (b < 584) {
        int mat = b / 146, grp = b % 146;
        const float* W; const float* vec;
        if (mat == 0)      { W = Wr; vec = g_mix + 3 * H; }   // r <- mr
        else if (mat == 1) { W = Wk; vec = g_mix + 1 * H; }   // k <- mk
        else if (mat == 2) { W = Wv; vec = g_mix + 2 * H; }   // v <- mv
        else               { W = Wg; vec = g_mix + 4 * H; }   // g <- mg
        {
            const float4* V4 = (const float4*)vec;
            float4* S4 = (float4*)sv;
#pragma unroll
            for (int i = 0; i < 4; i++)
                S4[tid + i * 256] = V4[tid + i * 256];
        }
        __syncthreads();
        const float4* S4 = (const float4*)sv;
        for (int i = warp; i < 29; i += 8) {
            int row = grp + 146 * i;
            if (row >= H) break;
            const float4* W4 = (const float4*)(W + (size_t)row * H);
            float acc = 0.f;
#pragma unroll
            for (int ii = 0; ii < 4; ii++) {
                float4 w[8];
#pragma unroll
                for (int j = 0; j < 8; j++)             // 8 front-batched LDG.128
                    w[j] = W4[(ii * 8 + j) * 32 + lane];
#pragma unroll
                for (int j = 0; j < 8; j++) {
                    float4 u = S4[(ii * 8 + j) * 32 + lane];
                    acc += w[j].x * u.x + w[j].y * u.y + w[j].z * u.z + w[j].w * u.w;
                }
            }
            for (int o = 16; o; o >>= 1) acc += __shfl_down_sync(~0u, acc, o);
            if (lane == 0) {
                if (mat == 0)      g_r[row] = acc;
                else if (mat == 1) g_k[row] = acc;
                else if (mat == 2) g_v[row] = acc;
                else               g_g[row] = acc / (1.f + expf(-acc)); // silu
            }
        }
    } else {
        // decay stage 1 partials: 8 blocks x 512 rows
        int qb = b - 584;
        int j0 = qb * 512;
        int t = tid & 127, sub = tid >> 7;
        float acc = 0.f;
        for (int j = j0 + sub; j < j0 + 512; j += 2)
            acc += g_mix[j] * dw1[j * TD + t];          // mw = mix[0]
        sv[tid] = acc;
        __syncthreads();
        if (sub == 0) g_zpart[qb][t] = sv[t] + sv[t + 128];
    }
    grid_bar(2);

    // ============ P4: per-head decay2/wkv/state/norm (blocks 0..63) ============
    if (b < 64) {
        int h = b;
        int j = tid & 63, p = tid >> 6;
        float* tz   = sv;            // [128]
        float* sr   = sv + 128;      // [64]
        float* sk   = sv + 192;      // [64]
        float* stdv = sv + 256;      // [64]
        float* red  = sv + 320;      // [64]
        float* part = sv + 384;      // [4][64]
        if (tid < TD) {
            float z = 0.f;
#pragma unroll
            for (int qq = 0; qq < 8; qq++) z += g_zpart[qq][tid];
            tz[tid] = tanhf(z);
        }
        __syncthreads();
        int gi = h * HS + j;
        float dacc = 0.f;
#pragma unroll
        for (int t = p * 32; t < p * 32 + 32; t++)
            dacc += tz[t] * dw2[(size_t)t * H + gi];
        part[p * 64 + j] = dacc;
        __syncthreads();
        if (p == 0) {
            float d = part[j] + part[64 + j] + part[128 + j] + part[192 + j] + tdec[gi];
            d = fminf(fmaxf(d, -9.72f), 2.27f);
            stdv[j] = expf(-expf(d));
            float rs = g_r[gi], ks = g_k[gi];
            sr[j] = rs; sk[j] = ks;
            red[j] = rs * ks * tfirst[gi];
        }
        __syncthreads();
        float a = 0.f;
#pragma unroll
        for (int t = 0; t < HS; t++) a += red[t];
        float vs = g_v[gi];
        const float* s2 = state2 + (size_t)h * HS * HS;
        float* s2o = out + 2 * H + (size_t)h * HS * HS;  // output #3: state2_out
        float acc2 = 0.f;
#pragma unroll
        for (int i = p * 16; i < p * 16 + 16; i++) {
            float s2v = s2[i * HS + j];
            acc2 += sr[i] * s2v;
            s2o[i * HS + j] = sk[i] * vs + s2v * stdv[i];
        }
        __syncthreads();
        part[p * 64 + j] = acc2;
        __syncthreads();
        if (p == 0) {
            float oj = a * vs + part[j] + part[64 + j] + part[128 + j] + part[192 + j];
            red[j] = oj;
        }
        __syncthreads();
        if (p == 0) {
            float s = 0.f, q = 0.f;
#pragma unroll
            for (int t = 0; t < HS; t++) { float u = red[t]; s += u; q += u * u; }
            float mu = s * (1.f / HS);
            float var = q * (1.f / HS) - mu * mu;
            float nj = (red[j] - mu) * rsqrtf(var + EPS);
            g_og[gi] = (nj * lnxw[gi] + lnxb[gi]) * g_g[gi];
        }
    }
    grid_bar(3);

    // ============ P5: out = x + og @ Wo.T (blocks 0..511, 1 row/warp) ============
    if (b < 512) {
        {
            const float4* V4 = (const float4*)g_og;
            float4* S4 = (float4*)sv;
#pragma unroll
            for (int i = 0; i < 4; i++)
                S4[tid + i * 256] = V4[tid + i * 256];
        }
        __syncthreads();
        const float4* S4 = (const float4*)sv;
        int row = b * 8 + warp;
        const float4* W4 = (const float4*)(Wo + (size_t)row * H);
        float acc = 0.f;
#pragma unroll
        for (int ii = 0; ii < 4; ii++) {
            float4 w[8];
#pragma unroll
            for (int jj = 0; jj < 8; jj++)
                w[jj] = W4[(ii * 8 + jj) * 32 + lane];
#pragma unroll
            for (int jj = 0; jj < 8; jj++) {
                float4 u = S4[(ii * 8 + jj) * 32 + lane];
                acc += w[jj].x * u.x + w[jj].y * u.y + w[jj].z * u.z + w[jj].w * u.w;
            }
        }
        for (int o = 16; o; o >>= 1) acc += __shfl_down_sync(~0u, acc, o);
        if (lane == 0) out[row] = x[row] + acc;
    }

    // ============ final arrive + counter reset (leaves zeros for next launch) ====
    __syncthreads();
    if (tid == 0) {
        __threadfence();
        atomicAdd(&g_barctr[4], 1);
        if (b == 0) {
            while (*((volatile int*)&g_barctr[4]) < NBLK) __nanosleep(128);
#pragma unroll
            for (int i = 0; i < 8; i++) g_barctr[i] = 0;
        }
    }
}

extern "C" void kernel_launch(void* const* d_in, const int* in_sizes, int n_in,
                              void* d_out, int out_size) {
    const float* x       = (const float*)d_in[0];
    const float* state1  = (const float*)d_in[1];
    const float* state2  = (const float*)d_in[2];
    const float* ln1_w   = (const float*)d_in[3];
    const float* ln1_b   = (const float*)d_in[4];
    const float* tmx     = (const float*)d_in[5];
    const float* tmaa    = (const float*)d_in[6];
    const float* maa_w1  = (const float*)d_in[7];
    const float* maa_w2  = (const float*)d_in[8];
    const float* tdec    = (const float*)d_in[9];
    const float* tfirst  = (const float*)d_in[10];
    const float* dw1     = (const float*)d_in[11];
    const float* dw2     = (const float*)d_in[12];
    const float* Wr      = (const float*)d_in[13];
    const float* Wk      = (const float*)d_in[14];
    const float* Wv      = (const float*)d_in[15];
    const float* Wg      = (const float*)d_in[16];
    const float* Wo      = (const float*)d_in[17];
    const float* lnx_w   = (const float*)d_in[18];
    const float* lnx_b   = (const float*)d_in[19];
    float* out = (float*)d_out;

    mega<<<NBLK, NTHR>>>(x, state1, state2, ln1_w, ln1_b, tmx, tmaa,
                         maa_w1, maa_w2, tdec, tfirst, dw1, dw2,
                         Wr, Wk, Wv, Wg, Wo, lnx_w, lnx_b, out);
}

// round 6
// speedup vs baseline: 1.1221x; 1.1221x over previous
#include <cuda_runtime.h>
#include <math.h>

#define H   4096
#define HS  64
#define NH  64
#define TM  64
#define TD  128
#define EPS 1e-5f

// ---------------- scratch ----------------
__device__ __align__(16) float g_xl[H];
__device__ __align__(16) float g_sx[H];
__device__ __align__(16) float g_mix[5 * H];
__device__ __align__(16) float g_r[H];
__device__ __align__(16) float g_k[H];
__device__ __align__(16) float g_v[H];
__device__ __align__(16) float g_g[H];
__device__ __align__(16) float g_og[H];
__device__ __align__(16) float g_ypart[128][5 * TM];  // K12 partials
__device__ __align__(16) float g_z128[TD];

// ---------------- K12: LN (redundant stats per block) + y320 partials ----------------
__global__ void __launch_bounds__(256) k12_ln_down(
        const float* __restrict__ x,      const float* __restrict__ state1,
        const float* __restrict__ ln1w,   const float* __restrict__ ln1b,
        const float* __restrict__ tmx,    const float* __restrict__ w1,
        float* __restrict__ out) {
    __shared__ float ssr[16];
    __shared__ float sxm[32];
    int b = blockIdx.x, tid = threadIdx.x;     // 128 blocks x 256 thr
    int warp = tid >> 5, lane = tid & 31;

    float vals[16];
    float s = 0.f, q = 0.f;
#pragma unroll
    for (int i = 0; i < 16; i++) {
        float v = x[tid + i * 256];
        vals[i] = v; s += v; q += v * v;
    }
    for (int o = 16; o; o >>= 1) { s += __shfl_down_sync(~0u, s, o); q += __shfl_down_sync(~0u, q, o); }
    if (lane == 0) { ssr[warp] = s; ssr[warp + 8] = q; }
    __syncthreads();
    if (tid < 8) {
        float a = ssr[tid], c = ssr[tid + 8];
        for (int o = 4; o; o >>= 1) { a += __shfl_down_sync(0xff, a, o); c += __shfl_down_sync(0xff, c, o); }
        if (tid == 0) { ssr[0] = a; ssr[8] = c; }
    }
    __syncthreads();
    float mu = ssr[0] * (1.f / H);
    float var = ssr[8] * (1.f / H) - mu * mu;
    float inv = rsqrtf(var + EPS);

    // this block's 32 rows of xm
    int j0 = b * 32;
    if (tid < 32) {
        int idx = j0 + tid;
        float xl = (x[idx] - mu) * inv * ln1w[idx] + ln1b[idx];
        float sxv = state1[idx] - xl;
        sxm[tid] = xl + sxv * tmx[idx];
    }
    // block 0 also publishes full xl/sx + output #2
    if (b == 0) {
#pragma unroll
        for (int i = 0; i < 16; i++) {
            int idx = tid + i * 256;
            float xl = (vals[i] - mu) * inv * ln1w[idx] + ln1b[idx];
            g_xl[idx] = xl;
            g_sx[idx] = state1[idx] - xl;
            out[H + idx] = xl;
        }
    }
    __syncthreads();

    // y320 partial over 32 rows
    for (int c = tid; c < 320; c += 256) {
        float acc = 0.f;
#pragma unroll 8
        for (int j = 0; j < 32; j++)
            acc += sxm[j] * w1[(j0 + j) * 320 + c];
        g_ypart[b][c] = acc;
    }
}

// ---------------- K3: mixes = xl + sx*(lora_up + time_maa), 160 blocks x 128 ----------------
__global__ void __launch_bounds__(128) k3_maa_up(const float* __restrict__ w2,
                                                 const float* __restrict__ tmaa) {
    cudaGridDependencySynchronize();
    int b = blockIdx.x, tid = threadIdx.x;
    int f = b >> 5;                        // 32 blocks per mix
    int gid = b * 128 + tid;
    int h = gid & (H - 1);
    __shared__ float ty[TM];
    if (tid < TM) {
        float y = 0.f;
#pragma unroll 8
        for (int qq = 0; qq < 128; qq++) y += g_ypart[qq][f * TM + tid];
        ty[tid] = tanhf(y);
    }
    __syncthreads();
    const float* base = w2 + (size_t)f * TM * H + h;
    float acc = 0.f;
#pragma unroll
    for (int t = 0; t < TM; t++) acc += ty[t] * base[(size_t)t * H];
    g_mix[gid] = g_xl[h] + g_sx[h] * (acc + tmaa[gid]);
}

// ---------------- K4: 4 big GEMVs + decay stage 1 ----------------
__global__ void __launch_bounds__(256) k4_gemv4(
        const float* __restrict__ Wr, const float* __restrict__ Wk,
        const float* __restrict__ Wv, const float* __restrict__ Wg,
        const float* __restrict__ dw1) {
    cudaGridDependencySynchronize();
    __shared__ float sv[H];          // 16KB vector tile
    __shared__ float sh[256];

    if (blockIdx.x >= 2048) {
        // decay stage 1: z128 = mw @ decay_w1 (4096 x 128), 16 blocks x 256 rows
        int bb = blockIdx.x - 2048;
        int j0 = bb * 256;
        int t = threadIdx.x & 127;
        int sub = threadIdx.x >> 7;
        float acc = 0.f;
        for (int j = j0 + sub; j < j0 + 256; j += 2)
            acc += g_mix[j] * dw1[j * TD + t];   // mw = mix[0]
        sh[threadIdx.x] = acc;
        __syncthreads();
        if (sub == 0) atomicAdd(&g_z128[t], sh[t] + sh[t + 128]);
        return;
    }

    int mat = blockIdx.x >> 9;                   // 512 blocks per matrix
    const float* W; const float* vec;
    if (mat == 0)      { W = Wr; vec = g_mix + 3 * H; }   // r <- mr
    else if (mat == 1) { W = Wk; vec = g_mix + 1 * H; }   // k <- mk
    else if (mat == 2) { W = Wv; vec = g_mix + 2 * H; }   // v <- mv
    else               { W = Wg; vec = g_mix + 4 * H; }   // g <- mg

    int warp = threadIdx.x >> 5, lane = threadIdx.x & 31;
    int row = (blockIdx.x & 511) * 8 + warp;
    const float4* W4 = (const float4*)(W + (size_t)row * H);

    // first weight batch in flight BEFORE staging (hides staging bubble)
    float4 w[8];
#pragma unroll
    for (int j = 0; j < 8; j++) w[j] = W4[j * 32 + lane];

    {
        const float4* V4 = (const float4*)vec;
        float4* S4 = (float4*)sv;
#pragma unroll
        for (int i = 0; i < 4; i++)
            S4[threadIdx.x + i * 256] = V4[threadIdx.x + i * 256];
    }
    __syncthreads();

    const float4* S4 = (const float4*)sv;
    float acc = 0.f;
#pragma unroll
    for (int ii = 0; ii < 4; ii++) {
#pragma unroll
        for (int j = 0; j < 8; j++) {
            float4 u = S4[(ii * 8 + j) * 32 + lane];
            acc += w[j].x * u.x + w[j].y * u.y + w[j].z * u.z + w[j].w * u.w;
        }
        if (ii < 3) {
#pragma unroll
            for (int j = 0; j < 8; j++)              // next batch, 8 in flight
                w[j] = W4[((ii + 1) * 8 + j) * 32 + lane];
        }
    }
    for (int o = 16; o; o >>= 1) acc += __shfl_down_sync(~0u, acc, o);
    if (lane == 0) {
        if (mat == 0)      g_r[row] = acc;
        else if (mat == 1) g_k[row] = acc;
        else if (mat == 2) g_v[row] = acc;
        else               g_g[row] = acc / (1.f + expf(-acc)); // silu
    }
}

// ---------------- K5: per-head decay/wkv/state/norm (256 threads/head) ----------------
__global__ void k5_heads(const float* __restrict__ state2,
                         const float* __restrict__ dw2,
                         const float* __restrict__ tdec,
                         const float* __restrict__ tfirst,
                         const float* __restrict__ lnxw,
                         const float* __restrict__ lnxb,
                         float* __restrict__ out) {
    cudaGridDependencySynchronize();
    int h = blockIdx.x;                 // 64 heads
    int tid = threadIdx.x;              // 256 threads
    int j = tid & 63;                   // column within head
    int p = tid >> 6;                   // 0..3 partition
    const float* s2 = state2 + (size_t)h * HS * HS;

    __shared__ float tz[TD], sr[HS], sk[HS], std_[HS], red[HS];
    __shared__ float part[4][HS];

    if (tid < TD) tz[tid] = tanhf(g_z128[tid]);
    __syncthreads();

    int gi = h * HS + j;

    float dacc = 0.f;
#pragma unroll
    for (int t = p * 32; t < p * 32 + 32; t++)
        dacc += tz[t] * dw2[(size_t)t * H + gi];
    part[p][j] = dacc;
    __syncthreads();
    if (p == 0) {
        float d = part[0][j] + part[1][j] + part[2][j] + part[3][j] + tdec[gi];
        d = fminf(fmaxf(d, -9.72f), 2.27f);
        std_[j] = expf(-expf(d));
        float rs = g_r[gi], ks = g_k[gi];
        sr[j] = rs; sk[j] = ks;
        red[j] = rs * ks * tfirst[gi];
    }
    __syncthreads();

    float a = 0.f;
#pragma unroll
    for (int t = 0; t < HS; t++) a += red[t];   // broadcast reads

    float vs = g_v[gi];
    float* s2o = out + 2 * H + (size_t)h * HS * HS;   // output #3: state2_out
    float acc2 = 0.f;
#pragma unroll
    for (int i = p * 16; i < p * 16 + 16; i++) {
        float s2v = s2[i * HS + j];
        acc2 += sr[i] * s2v;
        s2o[i * HS + j] = sk[i] * vs + s2v * std_[i];
    }
    part[p][j] = acc2;
    __syncthreads();

    if (p == 0) {
        float oj = a * vs + part[0][j] + part[1][j] + part[2][j] + part[3][j];
        red[j] = oj;
    }
    __syncthreads();
    if (p == 0) {
        float s = 0.f, q = 0.f;
#pragma unroll
        for (int t = 0; t < HS; t++) { float u = red[t]; s += u; q += u * u; }
        float mu = s * (1.f / HS);
        float var = q * (1.f / HS) - mu * mu;
        float nj = (red[j] - mu) * rsqrtf(var + EPS);
        g_og[gi] = (nj * lnxw[gi] + lnxb[gi]) * g_g[gi];
    }
}

// ---------------- K6: out = x + og @ Wo.T ----------------
__global__ void __launch_bounds__(256) k6_out(const float* __restrict__ Wo,
                                              const float* __restrict__ x,
                                              float* __restrict__ out) {
    cudaGridDependencySynchronize();
    __shared__ float sv[H];
    int warp = threadIdx.x >> 5, lane = threadIdx.x & 31;
    int row = blockIdx.x * 8 + warp;
    const float4* W4 = (const float4*)(Wo + (size_t)row * H);

    float4 w[8];
#pragma unroll
    for (int jj = 0; jj < 8; jj++) w[jj] = W4[jj * 32 + lane];

    {
        const float4* V4 = (const float4*)g_og;
        float4* S4 = (float4*)sv;
#pragma unroll
        for (int i = 0; i < 4; i++)
            S4[threadIdx.x + i * 256] = V4[threadIdx.x + i * 256];
    }
    __syncthreads();

    const float4* S4 = (const float4*)sv;
    float acc = 0.f;
#pragma unroll
    for (int ii = 0; ii < 4; ii++) {
#pragma unroll
        for (int jj = 0; jj < 8; jj++) {
            float4 u = S4[(ii * 8 + jj) * 32 + lane];
            acc += w[jj].x * u.x + w[jj].y * u.y + w[jj].z * u.z + w[jj].w * u.w;
        }
        if (ii < 3) {
#pragma unroll
            for (int jj = 0; jj < 8; jj++)
                w[jj] = W4[((ii + 1) * 8 + jj) * 32 + lane];
        }
    }
    for (int o = 16; o; o >>= 1) acc += __shfl_down_sync(~0u, acc, o);
    if (lane == 0) out[row] = x[row] + acc;
}

// zero g_z128 before K4's atomics (tiny, fused into K12 grid is messy; separate graph node is ~free)
__global__ void k0_zero() { g_z128[threadIdx.x] = 0.f; }

// ---------------- launch helpers ----------------
template <typename... Args>
static void launch_pdl(void (*kern)(Args...), dim3 grid, dim3 block, Args... args) {
    cudaLaunchConfig_t cfg = {};
    cfg.gridDim = grid;
    cfg.blockDim = block;
    cfg.dynamicSmemBytes = 0;
    cfg.stream = 0;
    cudaLaunchAttribute attr[1];
    attr[0].id = cudaLaunchAttributeProgrammaticStreamSerialization;
    attr[0].val.programmaticStreamSerializationAllowed = 1;
    cfg.attrs = attr;
    cfg.numAttrs = 1;
    cudaLaunchKernelEx(&cfg, kern, args...);
}

extern "C" void kernel_launch(void* const* d_in, const int* in_sizes, int n_in,
                              void* d_out, int out_size) {
    const float* x       = (const float*)d_in[0];
    const float* state1  = (const float*)d_in[1];
    const float* state2  = (const float*)d_in[2];
    const float* ln1_w   = (const float*)d_in[3];
    const float* ln1_b   = (const float*)d_in[4];
    const float* tmx     = (const float*)d_in[5];
    const float* tmaa    = (const float*)d_in[6];
    const float* maa_w1  = (const float*)d_in[7];
    const float* maa_w2  = (const float*)d_in[8];
    const float* tdec    = (const float*)d_in[9];
    const float* tfirst  = (const float*)d_in[10];
    const float* dw1     = (const float*)d_in[11];
    const float* dw2     = (const float*)d_in[12];
    const float* Wr      = (const float*)d_in[13];
    const float* Wk      = (const float*)d_in[14];
    const float* Wv      = (const float*)d_in[15];
    const float* Wg      = (const float*)d_in[16];
    const float* Wo      = (const float*)d_in[17];
    const float* lnx_w   = (const float*)d_in[18];
    const float* lnx_b   = (const float*)d_in[19];
    float* out = (float*)d_out;

    k0_zero<<<1, TD>>>();
    k12_ln_down<<<128, 256>>>(x, state1, ln1_w, ln1_b, tmx, maa_w1, out);
    launch_pdl(k3_maa_up, dim3(160), dim3(128), maa_w2, tmaa);
    launch_pdl(k4_gemv4, dim3(2064), dim3(256), Wr, Wk, Wv, Wg, dw1);
    launch_pdl(k5_heads, dim3(64), dim3(256), state2, dw2, tdec, tfirst, lnx_w, lnx_b, out);
    launch_pdl(k6_out, dim3(512), dim3(256), Wo, x, out);
}

// round 8
// speedup vs baseline: 1.1777x; 1.0496x over previous
#include <cuda_runtime.h>
#include <stdint.h>
#include <math.h>

#define H   4096
#define HS  64
#define NH  64
#define TM  64
#define TD  128
#define EPS 1e-5f
#define CHUNK 512              // floats per row-chunk (2KB)
#define NCH   (H / CHUNK)      // 8 chunks

// ---------------- scratch ----------------
__device__ __align__(16) float g_xl[H];
__device__ __align__(16) float g_sx[H];
__device__ __align__(16) float g_xm[H];
__device__ __align__(16) float g_y320[5 * TM];
__device__ __align__(16) float g_mix[5 * H];
__device__ __align__(16) float g_r[H];
__device__ __align__(16) float g_k[H];
__device__ __align__(16) float g_v[H];
__device__ __align__(16) float g_g[H];
__device__ __align__(16) float g_z128[TD];
__device__ __align__(16) float g_og[H];

__device__ __forceinline__ uint32_t smem_u32(const void* p) {
    return (uint32_t)__cvta_generic_to_shared(p);
}
__device__ __forceinline__ void cp16(uint32_t d, const void* s) {
    asm volatile("cp.async.cg.shared.global [%0], [%1], 16;" :: "r"(d), "l"(s));
}

// ---------------- K1: LN(x), sx, xm, zero accumulators ----------------
__global__ void k1_ln(const float* __restrict__ x,
                      const float* __restrict__ state1,
                      const float* __restrict__ ln1w,
                      const float* __restrict__ ln1b,
                      const float* __restrict__ tmx,
                      float* __restrict__ out) {
    __shared__ float ssum[32], ssq[32];
    int tid = threadIdx.x;              // 1024 threads
    float vals[4];
    float s = 0.f, q = 0.f;
#pragma unroll
    for (int i = 0; i < 4; i++) {
        float v = x[tid + i * 1024];
        vals[i] = v; s += v; q += v * v;
    }
    for (int o = 16; o; o >>= 1) { s += __shfl_down_sync(~0u, s, o); q += __shfl_down_sync(~0u, q, o); }
    if ((tid & 31) == 0) { ssum[tid >> 5] = s; ssq[tid >> 5] = q; }
    __syncthreads();
    if (tid < 32) {
        float a = ssum[tid], b = ssq[tid];
        for (int o = 16; o; o >>= 1) { a += __shfl_down_sync(~0u, a, o); b += __shfl_down_sync(~0u, b, o); }
        if (tid == 0) { ssum[0] = a; ssq[0] = b; }
    }
    __syncthreads();
    float mu = ssum[0] * (1.f / H);
    float var = ssq[0] * (1.f / H) - mu * mu;
    float inv = rsqrtf(var + EPS);
#pragma unroll
    for (int i = 0; i < 4; i++) {
        int idx = tid + i * 1024;
        float xl = (vals[i] - mu) * inv * ln1w[idx] + ln1b[idx];
        g_xl[idx] = xl;
        out[H + idx] = xl;                       // output #2: xl
        float sx = state1[idx] - xl;
        g_sx[idx] = sx;
        g_xm[idx] = xl + sx * tmx[idx];
    }
    if (tid < 5 * TM) g_y320[tid] = 0.f;
    if (tid < TD)     g_z128[tid] = 0.f;
}

// ---------------- K2: y320 = xm @ maa_w1 (4096 x 320), 128 blocks ----------------
__global__ void k2_maa_down(const float* __restrict__ w1) {
    int t = threadIdx.x;                 // 320 threads
    int j0 = blockIdx.x * 32;            // 128 blocks x 32 rows
    float acc = 0.f;
#pragma unroll 8
    for (int j = j0; j < j0 + 32; j++)
        acc += g_xm[j] * w1[j * 320 + t];
    atomicAdd(&g_y320[t], acc);
}

// ---------------- K3: mixes = xl + sx*(lora_up + time_maa) ----------------
__global__ void k3_maa_up(const float* __restrict__ w2,
                          const float* __restrict__ tmaa) {
    int gid = blockIdx.x * 256 + threadIdx.x;   // 80 blocks * 256 = 5*4096
    int f = gid >> 12;
    int h = gid & (H - 1);
    __shared__ float ty[TM];
    if (threadIdx.x < TM) ty[threadIdx.x] = tanhf(g_y320[f * TM + threadIdx.x]);
    __syncthreads();
    const float* base = w2 + (size_t)f * TM * H + h;
    float acc = 0.f;
#pragma unroll
    for (int t = 0; t < TM; t++) acc += ty[t] * base[(size_t)t * H];
    g_mix[gid] = g_xl[h] + g_sx[h] * (acc + tmaa[gid]);
}

// ---------------- K4: 4 big GEMVs (cp.async pipeline) + decay stage 1 ----------------
__global__ void __launch_bounds__(256) k4_gemv4(
        const float* __restrict__ Wr, const float* __restrict__ Wk,
        const float* __restrict__ Wv, const float* __restrict__ Wg,
        const float* __restrict__ dw1) {
    __shared__ float sv[H];                    // 16KB vector tile
    __shared__ float stage[2][8 * CHUNK];      // 2 x 16KB weight stages
    __shared__ float sh[256];

    if (blockIdx.x >= 2048) {
        // decay stage 1: z128 = mw @ decay_w1 (4096 x 128), 16 blocks x 256 rows
        int bb = blockIdx.x - 2048;
        int j0 = bb * 256;
        int t = threadIdx.x & 127;
        int sub = threadIdx.x >> 7;
        float acc = 0.f;
        for (int j = j0 + sub; j < j0 + 256; j += 2)
            acc += g_mix[j] * dw1[j * TD + t];   // mw = mix[0]
        sh[threadIdx.x] = acc;
        __syncthreads();
        if (sub == 0) atomicAdd(&g_z128[t], sh[t] + sh[t + 128]);
        return;
    }

    int mat = blockIdx.x >> 9;                   // 512 blocks per matrix
    const float* W; const float* vec;
    if (mat == 0)      { W = Wr; vec = g_mix + 3 * H; }   // r <- mr
    else if (mat == 1) { W = Wk; vec = g_mix + 1 * H; }   // k <- mk
    else if (mat == 2) { W = Wv; vec = g_mix + 2 * H; }   // v <- mv
    else               { W = Wg; vec = g_mix + 4 * H; }   // g <- mg

    int tid = threadIdx.x;
    int warp = tid >> 5, lane = tid & 31;
    int row0 = (blockIdx.x & 511) * 8;
    const float* Wbase = W + (size_t)row0 * H;

    // thread's 4 copy slots: float4 idx tid, tid+256, tid+512, tid+768 of the 1024-float4 stage
    int cr[4], cc[4];
#pragma unroll
    for (int i = 0; i < 4; i++) {
        int idx = tid + i * 256;
        cr[i] = idx >> 7;            // row 0..7
        cc[i] = idx & 127;           // float4 col in chunk
    }
    uint32_t sb0 = smem_u32(&stage[0][0]);
    uint32_t sb1 = smem_u32(&stage[1][0]);

    // prologue: issue chunks 0 and 1
#pragma unroll
    for (int i = 0; i < 4; i++)
        cp16(sb0 + (tid + i * 256) * 16,
             (const float4*)(Wbase + (size_t)cr[i] * H + 0 * CHUNK) + cc[i]);
    asm volatile("cp.async.commit_group;" ::: "memory");
#pragma unroll
    for (int i = 0; i < 4; i++)
        cp16(sb1 + (tid + i * 256) * 16,
             (const float4*)(Wbase + (size_t)cr[i] * H + 1 * CHUNK) + cc[i]);
    asm volatile("cp.async.commit_group;" ::: "memory");

    // stage the vector (regular loads, overlapped with cp.async)
    {
        const float4* V4 = (const float4*)vec;
        float4* S4 = (float4*)sv;
#pragma unroll
        for (int i = 0; i < 4; i++)
            S4[tid + i * 256] = V4[tid + i * 256];
    }

    float acc = 0.f;
#pragma unroll
    for (int c = 0; c < NCH; c++) {
        if (c + 1 < NCH) asm volatile("cp.async.wait_group 1;" ::: "memory");
        else             asm volatile("cp.async.wait_group 0;" ::: "memory");
        __syncthreads();
        const float4* SB = (const float4*)&stage[c & 1][warp * CHUNK];
        const float4* SV = (const float4*)&sv[c * CHUNK];
#pragma unroll
        for (int i = 0; i < 4; i++) {
            float4 w = SB[lane + i * 32];
            float4 u = SV[lane + i * 32];
            acc += w.x * u.x + w.y * u.y + w.z * u.z + w.w * u.w;
        }
        __syncthreads();
        if (c + 2 < NCH) {
            uint32_t sb = (c & 1) ? sb1 : sb0;   // reuse the buffer just consumed
#pragma unroll
            for (int i = 0; i < 4; i++)
                cp16(sb + (tid + i * 256) * 16,
                     (const float4*)(Wbase + (size_t)cr[i] * H + (c + 2) * CHUNK) + cc[i]);
            asm volatile("cp.async.commit_group;" ::: "memory");
        }
    }

    for (int o = 16; o; o >>= 1) acc += __shfl_down_sync(~0u, acc, o);
    if (lane == 0) {
        int row = row0 + warp;
        if (mat == 0)      g_r[row] = acc;
        else if (mat == 1) g_k[row] = acc;
        else if (mat == 2) g_v[row] = acc;
        else               g_g[row] = acc / (1.f + expf(-acc)); // silu
    }
}

// ---------------- K5: per-head decay/wkv/state/norm (256 threads/head) ----------------
__global__ void k5_heads(const float* __restrict__ state2,
                         const float* __restrict__ dw2,
                         const float* __restrict__ tdec,
                         const float* __restrict__ tfirst,
                         const float* __restrict__ lnxw,
                         const float* __restrict__ lnxb,
                         float* __restrict__ out) {
    int h = blockIdx.x;                 // 64 heads
    int tid = threadIdx.x;              // 256 threads
    int j = tid & 63;                   // column within head
    int p = tid >> 6;                   // 0..3 partition
    const float* s2 = state2 + (size_t)h * HS * HS;

    __shared__ float tz[TD], sr[HS], sk[HS], std_[HS], red[HS];
    __shared__ float part[4][HS];

    if (tid < TD) tz[tid] = tanhf(g_z128[tid]);
    __syncthreads();

    int gi = h * HS + j;

    float dacc = 0.f;
#pragma unroll
    for (int t = p * 32; t < p * 32 + 32; t++)
        dacc += tz[t] * dw2[(size_t)t * H + gi];
    part[p][j] = dacc;
    __syncthreads();
    if (p == 0) {
        float d = part[0][j] + part[1][j] + part[2][j] + part[3][j] + tdec[gi];
        d = fminf(fmaxf(d, -9.72f), 2.27f);
        std_[j] = expf(-expf(d));
        float rs = g_r[gi], ks = g_k[gi];
        sr[j] = rs; sk[j] = ks;
        red[j] = rs * ks * tfirst[gi];
    }
    __syncthreads();

    float a = 0.f;
#pragma unroll
    for (int t = 0; t < HS; t++) a += red[t];   // broadcast reads

    float vs = g_v[gi];
    float* s2o = out + 2 * H + (size_t)h * HS * HS;   // output #3: state2_out
    float acc2 = 0.f;
#pragma unroll
    for (int i = p * 16; i < p * 16 + 16; i++) {
        float s2v = s2[i * HS + j];
        acc2 += sr[i] * s2v;
        s2o[i * HS + j] = sk[i] * vs + s2v * std_[i];
    }
    part[p][j] = acc2;
    __syncthreads();

    if (p == 0) {
        float oj = a * vs + part[0][j] + part[1][j] + part[2][j] + part[3][j];
        red[j] = oj;
    }
    __syncthreads();
    if (p == 0) {
        float s = 0.f, q = 0.f;
#pragma unroll
        for (int t = 0; t < HS; t++) { float u = red[t]; s += u; q += u * u; }
        float mu = s * (1.f / HS);
        float var = q * (1.f / HS) - mu * mu;
        float nj = (red[j] - mu) * rsqrtf(var + EPS);
        g_og[gi] = (nj * lnxw[gi] + lnxb[gi]) * g_g[gi];
    }
}

// ---------------- K6: out = x + og @ Wo.T (cp.async pipeline) ----------------
__global__ void __launch_bounds__(256) k6_out(const float* __restrict__ Wo,
                                              const float* __restrict__ x,
                                              float* __restrict__ out) {
    __shared__ float sv[H];
    __shared__ float stage[2][8 * CHUNK];
    int tid = threadIdx.x;
    int warp = tid >> 5, lane = tid & 31;
    int row0 = blockIdx.x * 8;
    const float* Wbase = Wo + (size_t)row0 * H;

    int cr[4], cc[4];
#pragma unroll
    for (int i = 0; i < 4; i++) {
        int idx = tid + i * 256;
        cr[i] = idx >> 7;
        cc[i] = idx & 127;
    }
    uint32_t sb0 = smem_u32(&stage[0][0]);
    uint32_t sb1 = smem_u32(&stage[1][0]);

#pragma unroll
    for (int i = 0; i < 4; i++)
        cp16(sb0 + (tid + i * 256) * 16,
             (const float4*)(Wbase + (size_t)cr[i] * H + 0 * CHUNK) + cc[i]);
    asm volatile("cp.async.commit_group;" ::: "memory");
#pragma unroll
    for (int i = 0; i < 4; i++)
        cp16(sb1 + (tid + i * 256) * 16,
             (const float4*)(Wbase + (size_t)cr[i] * H + 1 * CHUNK) + cc[i]);
    asm volatile("cp.async.commit_group;" ::: "memory");

    {
        const float4* V4 = (const float4*)g_og;
        float4* S4 = (float4*)sv;
#pragma unroll
        for (int i = 0; i < 4; i++)
            S4[tid + i * 256] = V4[tid + i * 256];
    }

    float acc = 0.f;
#pragma unroll
    for (int c = 0; c < NCH; c++) {
        if (c + 1 < NCH) asm volatile("cp.async.wait_group 1;" ::: "memory");
        else             asm volatile("cp.async.wait_group 0;" ::: "memory");
        __syncthreads();
        const float4* SB = (const float4*)&stage[c & 1][warp * CHUNK];
        const float4* SV = (const float4*)&sv[c * CHUNK];
#pragma unroll
        for (int i = 0; i < 4; i++) {
            float4 w = SB[lane + i * 32];
            float4 u = SV[lane + i * 32];
            acc += w.x * u.x + w.y * u.y + w.z * u.z + w.w * u.w;
        }
        __syncthreads();
        if (c + 2 < NCH) {
            uint32_t sb = (c & 1) ? sb1 : sb0;
#pragma unroll
            for (int i = 0; i < 4; i++)
                cp16(sb + (tid + i * 256) * 16,
                     (const float4*)(Wbase + (size_t)cr[i] * H + (c + 2) * CHUNK) + cc[i]);
            asm volatile("cp.async.commit_group;" ::: "memory");
        }
    }

    for (int o = 16; o; o >>= 1) acc += __shfl_down_sync(~0u, acc, o);
    if (lane == 0) {
        int row = row0 + warp;
        out[row] = x[row] + acc;
    }
}

// ---------------- launch ----------------
extern "C" void kernel_launch(void* const* d_in, const int* in_sizes, int n_in,
                              void* d_out, int out_size) {
    const float* x       = (const float*)d_in[0];
    const float* state1  = (const float*)d_in[1];
    const float* state2  = (const float*)d_in[2];
    const float* ln1_w   = (const float*)d_in[3];
    const float* ln1_b   = (const float*)d_in[4];
    const float* tmx     = (const float*)d_in[5];
    const float* tmaa    = (const float*)d_in[6];
    const float* maa_w1  = (const float*)d_in[7];
    const float* maa_w2  = (const float*)d_in[8];
    const float* tdec    = (const float*)d_in[9];
    const float* tfirst  = (const float*)d_in[10];
    const float* dw1     = (const float*)d_in[11];
    const float* dw2     = (const float*)d_in[12];
    const float* Wr      = (const float*)d_in[13];
    const float* Wk      = (const float*)d_in[14];
    const float* Wv      = (const float*)d_in[15];
    const float* Wg      = (const float*)d_in[16];
    const float* Wo      = (const float*)d_in[17];
    const float* lnx_w   = (const float*)d_in[18];
    const float* lnx_b   = (const float*)d_in[19];
    float* out = (float*)d_out;

    k1_ln<<<1, 1024>>>(x, state1, ln1_w, ln1_b, tmx, out);
    k2_maa_down<<<128, 320>>>(maa_w1);
    k3_maa_up<<<80, 256>>>(maa_w2, tmaa);
    k4_gemv4<<<2064, 256>>>(Wr, Wk, Wv, Wg, dw1);
    k5_heads<<<64, 256>>>(state2, dw2, tdec, tfirst, lnx_w, lnx_b, out);
    k6_out<<<512, 256>>>(Wo, x, out);
}

// round 9
// speedup vs baseline: 1.2830x; 1.0894x over previous
#include <cuda_runtime.h>
#include <stdint.h>
#include <math.h>

#define H   4096
#define HS  64
#define NH  64
#define TM  64
#define TD  128
#define EPS 1e-5f
#define CHUNK 256              // floats per row-chunk (1KB/row, 8KB/stage)
#define NCH   (H / CHUNK)      // 16 chunks
#define NSTG  3

// ---------------- scratch ----------------
__device__ __align__(16) float g_xl[H];
__device__ __align__(16) float g_sx[H];
__device__ __align__(16) float g_xm[H];
__device__ __align__(16) float g_y320[5 * TM];
__device__ __align__(16) float g_mix[5 * H];
__device__ __align__(16) float g_r[H];
__device__ __align__(16) float g_k[H];
__device__ __align__(16) float g_v[H];
__device__ __align__(16) float g_g[H];
__device__ __align__(16) float g_z128[TD];
__device__ __align__(16) float g_og[H];

__device__ __forceinline__ uint32_t smem_u32(const void* p) {
    return (uint32_t)__cvta_generic_to_shared(p);
}
__device__ __forceinline__ void cp16(uint32_t d, const void* s) {
    asm volatile("cp.async.cg.shared.global [%0], [%1], 16;" :: "r"(d), "l"(s));
}
__device__ __forceinline__ void cp_commit() {
    asm volatile("cp.async.commit_group;" ::: "memory");
}
template <int N>
__device__ __forceinline__ void cp_wait() {
    asm volatile("cp.async.wait_group %0;" :: "n"(N) : "memory");
}

// ---------------- K1: LN(x), sx, xm, zero accumulators ----------------
__global__ void k1_ln(const float* __restrict__ x,
                      const float* __restrict__ state1,
                      const float* __restrict__ ln1w,
                      const float* __restrict__ ln1b,
                      const float* __restrict__ tmx,
                      float* __restrict__ out) {
    __shared__ float ssum[32], ssq[32];
    int tid = threadIdx.x;              // 1024 threads
    float vals[4];
    float s = 0.f, q = 0.f;
#pragma unroll
    for (int i = 0; i < 4; i++) {
        float v = x[tid + i * 1024];
        vals[i] = v; s += v; q += v * v;
    }
    for (int o = 16; o; o >>= 1) { s += __shfl_down_sync(~0u, s, o); q += __shfl_down_sync(~0u, q, o); }
    if ((tid & 31) == 0) { ssum[tid >> 5] = s; ssq[tid >> 5] = q; }
    __syncthreads();
    if (tid < 32) {
        float a = ssum[tid], b = ssq[tid];
        for (int o = 16; o; o >>= 1) { a += __shfl_down_sync(~0u, a, o); b += __shfl_down_sync(~0u, b, o); }
        if (tid == 0) { ssum[0] = a; ssq[0] = b; }
    }
    __syncthreads();
    float mu = ssum[0] * (1.f / H);
    float var = ssq[0] * (1.f / H) - mu * mu;
    float inv = rsqrtf(var + EPS);
#pragma unroll
    for (int i = 0; i < 4; i++) {
        int idx = tid + i * 1024;
        float xl = (vals[i] - mu) * inv * ln1w[idx] + ln1b[idx];
        g_xl[idx] = xl;
        out[H + idx] = xl;                       // output #2: xl
        float sx = state1[idx] - xl;
        g_sx[idx] = sx;
        g_xm[idx] = xl + sx * tmx[idx];
    }
    if (tid < 5 * TM) g_y320[tid] = 0.f;
    if (tid < TD)     g_z128[tid] = 0.f;
}

// ---------------- K2: y320 = xm @ maa_w1 (4096 x 320), 128 blocks ----------------
__global__ void k2_maa_down(const float* __restrict__ w1) {
    cudaGridDependencySynchronize();
    int t = threadIdx.x;                 // 320 threads
    int j0 = blockIdx.x * 32;            // 128 blocks x 32 rows
    float acc = 0.f;
#pragma unroll 8
    for (int j = j0; j < j0 + 32; j++)
        acc += g_xm[j] * w1[j * 320 + t];
    atomicAdd(&g_y320[t], acc);
}

// ---------------- K3: mixes = xl + sx*(lora_up + time_maa) ----------------
__global__ void k3_maa_up(const float* __restrict__ w2,
                          const float* __restrict__ tmaa) {
    cudaGridDependencySynchronize();
    int gid = blockIdx.x * 256 + threadIdx.x;   // 80 blocks * 256 = 5*4096
    int f = gid >> 12;
    int h = gid & (H - 1);
    __shared__ float ty[TM];
    if (threadIdx.x < TM) ty[threadIdx.x] = tanhf(g_y320[f * TM + threadIdx.x]);
    __syncthreads();
    const float* base = w2 + (size_t)f * TM * H + h;
    float acc = 0.f;
#pragma unroll
    for (int t = 0; t < TM; t++) acc += ty[t] * base[(size_t)t * H];
    g_mix[gid] = g_xl[h] + g_sx[h] * (acc + tmaa[gid]);
}

// ---------------- K4: 4 big GEMVs (3-stage cp.async pipeline) + decay stage 1 ----------------
__global__ void __launch_bounds__(256) k4_gemv4(
        const float* __restrict__ Wr, const float* __restrict__ Wk,
        const float* __restrict__ Wv, const float* __restrict__ Wg,
        const float* __restrict__ dw1) {
    __shared__ float sv[H];                      // 16KB vector tile
    __shared__ float stage[NSTG][8 * CHUNK];     // 3 x 8KB weight stages
    __shared__ float sh[256];

    if (blockIdx.x >= 2048) {
        cudaGridDependencySynchronize();
        // decay stage 1: z128 = mw @ decay_w1 (4096 x 128), 16 blocks x 256 rows
        int bb = blockIdx.x - 2048;
        int j0 = bb * 256;
        int t = threadIdx.x & 127;
        int sub = threadIdx.x >> 7;
        float acc = 0.f;
        for (int j = j0 + sub; j < j0 + 256; j += 2)
            acc += g_mix[j] * dw1[j * TD + t];   // mw = mix[0]
        sh[threadIdx.x] = acc;
        __syncthreads();
        if (sub == 0) atomicAdd(&g_z128[t], sh[t] + sh[t + 128]);
        return;
    }

    int mat = blockIdx.x >> 9;                   // 512 blocks per matrix
    const float* W; const float* vec;
    if (mat == 0)      { W = Wr; vec = g_mix + 3 * H; }   // r <- mr
    else if (mat == 1) { W = Wk; vec = g_mix + 1 * H; }   // k <- mk
    else if (mat == 2) { W = Wv; vec = g_mix + 2 * H; }   // v <- mv
    else               { W = Wg; vec = g_mix + 4 * H; }   // g <- mg

    int tid = threadIdx.x;
    int warp = tid >> 5, lane = tid & 31;
    int row0 = (blockIdx.x & 511) * 8;
    const float* Wbase = W + (size_t)row0 * H;

    // copy mapping: 8 rows x 64 float4 per stage = 512 float4; 2 per thread
    int cr[2], cc[2];
#pragma unroll
    for (int i = 0; i < 2; i++) {
        int idx = tid + i * 256;
        cr[i] = idx >> 6;            // row 0..7
        cc[i] = idx & 63;            // float4 col in chunk
    }
    uint32_t sbase[NSTG];
#pragma unroll
    for (int s = 0; s < NSTG; s++) sbase[s] = smem_u32(&stage[s][0]);

    // prologue: weights are input-independent — issue BEFORE the PDL sync
#pragma unroll
    for (int s = 0; s < NSTG; s++) {
#pragma unroll
        for (int i = 0; i < 2; i++)
            cp16(sbase[s] + (tid + i * 256) * 16,
                 (const float4*)(Wbase + (size_t)cr[i] * H + s * CHUNK) + cc[i]);
        cp_commit();
    }

    cudaGridDependencySynchronize();

    // stage the vector (depends on K3)
    {
        const float4* V4 = (const float4*)vec;
        float4* S4 = (float4*)sv;
#pragma unroll
        for (int i = 0; i < 4; i++)
            S4[tid + i * 256] = V4[tid + i * 256];
    }

    float acc = 0.f;
#pragma unroll
    for (int c = 0; c < NCH; c++) {
        if (c < NCH - 2)      cp_wait<NSTG - 1>();
        else if (c == NCH - 2) cp_wait<1>();
        else                   cp_wait<0>();
        __syncthreads();
        const float4* SB = (const float4*)&stage[c % NSTG][warp * CHUNK];
        const float4* SV = (const float4*)&sv[c * CHUNK];
#pragma unroll
        for (int i = 0; i < 2; i++) {
            float4 w = SB[lane + i * 32];
            float4 u = SV[lane + i * 32];
            acc += w.x * u.x + w.y * u.y + w.z * u.z + w.w * u.w;
        }
        __syncthreads();
        if (c + NSTG < NCH) {
            uint32_t sb = sbase[c % NSTG];       // buffer just consumed
#pragma unroll
            for (int i = 0; i < 2; i++)
                cp16(sb + (tid + i * 256) * 16,
                     (const float4*)(Wbase + (size_t)cr[i] * H + (c + NSTG) * CHUNK) + cc[i]);
            cp_commit();
        }
    }

    for (int o = 16; o; o >>= 1) acc += __shfl_down_sync(~0u, acc, o);
    if (lane == 0) {
        int row = row0 + warp;
        if (mat == 0)      g_r[row] = acc;
        else if (mat == 1) g_k[row] = acc;
        else if (mat == 2) g_v[row] = acc;
        else               g_g[row] = acc / (1.f + expf(-acc)); // silu
    }
}

// ---------------- K5: per-head decay/wkv/state/norm (256 threads/head) ----------------
__global__ void k5_heads(const float* __restrict__ state2,
                         const float* __restrict__ dw2,
                         const float* __restrict__ tdec,
                         const float* __restrict__ tfirst,
                         const float* __restrict__ lnxw,
                         const float* __restrict__ lnxb,
                         float* __restrict__ out) {
    cudaGridDependencySynchronize();
    int h = blockIdx.x;                 // 64 heads
    int tid = threadIdx.x;              // 256 threads
    int j = tid & 63;                   // column within head
    int p = tid >> 6;                   // 0..3 partition
    const float* s2 = state2 + (size_t)h * HS * HS;

    __shared__ float tz[TD], sr[HS], sk[HS], std_[HS], red[HS];
    __shared__ float part[4][HS];

    if (tid < TD) tz[tid] = tanhf(g_z128[tid]);
    __syncthreads();

    int gi = h * HS + j;

    float dacc = 0.f;
#pragma unroll
    for (int t = p * 32; t < p * 32 + 32; t++)
        dacc += tz[t] * dw2[(size_t)t * H + gi];
    part[p][j] = dacc;
    __syncthreads();
    if (p == 0) {
        float d = part[0][j] + part[1][j] + part[2][j] + part[3][j] + tdec[gi];
        d = fminf(fmaxf(d, -9.72f), 2.27f);
        std_[j] = expf(-expf(d));
        float rs = g_r[gi], ks = g_k[gi];
        sr[j] = rs; sk[j] = ks;
        red[j] = rs * ks * tfirst[gi];
    }
    __syncthreads();

    float a = 0.f;
#pragma unroll
    for (int t = 0; t < HS; t++) a += red[t];   // broadcast reads

    float vs = g_v[gi];
    float* s2o = out + 2 * H + (size_t)h * HS * HS;   // output #3: state2_out
    float acc2 = 0.f;
#pragma unroll
    for (int i = p * 16; i < p * 16 + 16; i++) {
        float s2v = s2[i * HS + j];
        acc2 += sr[i] * s2v;
        s2o[i * HS + j] = sk[i] * vs + s2v * std_[i];
    }
    part[p][j] = acc2;
    __syncthreads();

    if (p == 0) {
        float oj = a * vs + part[0][j] + part[1][j] + part[2][j] + part[3][j];
        red[j] = oj;
    }
    __syncthreads();
    if (p == 0) {
        float s = 0.f, q = 0.f;
#pragma unroll
        for (int t = 0; t < HS; t++) { float u = red[t]; s += u; q += u * u; }
        float mu = s * (1.f / HS);
        float var = q * (1.f / HS) - mu * mu;
        float nj = (red[j] - mu) * rsqrtf(var + EPS);
        g_og[gi] = (nj * lnxw[gi] + lnxb[gi]) * g_g[gi];
    }
}

// ---------------- K6: out = x + og @ Wo.T (3-stage cp.async pipeline) ----------------
__global__ void __launch_bounds__(256) k6_out(const float* __restrict__ Wo,
                                              const float* __restrict__ x,
                                              float* __restrict__ out) {
    __shared__ float sv[H];
    __shared__ float stage[NSTG][8 * CHUNK];
    int tid = threadIdx.x;
    int warp = tid >> 5, lane = tid & 31;
    int row0 = blockIdx.x * 8;
    const float* Wbase = Wo + (size_t)row0 * H;

    int cr[2], cc[2];
#pragma unroll
    for (int i = 0; i < 2; i++) {
        int idx = tid + i * 256;
        cr[i] = idx >> 6;
        cc[i] = idx & 63;
    }
    uint32_t sbase[NSTG];
#pragma unroll
    for (int s = 0; s < NSTG; s++) sbase[s] = smem_u32(&stage[s][0]);

#pragma unroll
    for (int s = 0; s < NSTG; s++) {
#pragma unroll
        for (int i = 0; i < 2; i++)
            cp16(sbase[s] + (tid + i * 256) * 16,
                 (const float4*)(Wbase + (size_t)cr[i] * H + s * CHUNK) + cc[i]);
        cp_commit();
    }

    cudaGridDependencySynchronize();

    {
        const float4* V4 = (const float4*)g_og;
        float4* S4 = (float4*)sv;
#pragma unroll
        for (int i = 0; i < 4; i++)
            S4[tid + i * 256] = V4[tid + i * 256];
    }

    float acc = 0.f;
#pragma unroll
    for (int c = 0; c < NCH; c++) {
        if (c < NCH - 2)      cp_wait<NSTG - 1>();
        else if (c == NCH - 2) cp_wait<1>();
        else                   cp_wait<0>();
        __syncthreads();
        const float4* SB = (const float4*)&stage[c % NSTG][warp * CHUNK];
        const float4* SV = (const float4*)&sv[c * CHUNK];
#pragma unroll
        for (int i = 0; i < 2; i++) {
            float4 w = SB[lane + i * 32];
            float4 u = SV[lane + i * 32];
            acc += w.x * u.x + w.y * u.y + w.z * u.z + w.w * u.w;
        }
        __syncthreads();
        if (c + NSTG < NCH) {
            uint32_t sb = sbase[c % NSTG];
#pragma unroll
            for (int i = 0; i < 2; i++)
                cp16(sb + (tid + i * 256) * 16,
                     (const float4*)(Wbase + (size_t)cr[i] * H + (c + NSTG) * CHUNK) + cc[i]);
            cp_commit();
        }
    }

    for (int o = 16; o; o >>= 1) acc += __shfl_down_sync(~0u, acc, o);
    if (lane == 0) {
        int row = row0 + warp;
        out[row] = x[row] + acc;
    }
}

// ---------------- launch helpers ----------------
template <typename... Args>
static void launch_pdl(void (*kern)(Args...), dim3 grid, dim3 block, Args... args) {
    cudaLaunchConfig_t cfg = {};
    cfg.gridDim = grid;
    cfg.blockDim = block;
    cfg.dynamicSmemBytes = 0;
    cfg.stream = 0;
    cudaLaunchAttribute attr[1];
    attr[0].id = cudaLaunchAttributeProgrammaticStreamSerialization;
    attr[0].val.programmaticStreamSerializationAllowed = 1;
    cfg.attrs = attr;
    cfg.numAttrs = 1;
    cudaLaunchKernelEx(&cfg, kern, args...);
}

extern "C" void kernel_launch(void* const* d_in, const int* in_sizes, int n_in,
                              void* d_out, int out_size) {
    const float* x       = (const float*)d_in[0];
    const float* state1  = (const float*)d_in[1];
    const float* state2  = (const float*)d_in[2];
    const float* ln1_w   = (const float*)d_in[3];
    const float* ln1_b   = (const float*)d_in[4];
    const float* tmx     = (const float*)d_in[5];
    const float* tmaa    = (const float*)d_in[6];
    const float* maa_w1  = (const float*)d_in[7];
    const float* maa_w2  = (const float*)d_in[8];
    const float* tdec    = (const float*)d_in[9];
    const float* tfirst  = (const float*)d_in[10];
    const float* dw1     = (const float*)d_in[11];
    const float* dw2     = (const float*)d_in[12];
    const float* Wr      = (const float*)d_in[13];
    const float* Wk      = (const float*)d_in[14];
    const float* Wv      = (const float*)d_in[15];
    const float* Wg      = (const float*)d_in[16];
    const float* Wo      = (const float*)d_in[17];
    const float* lnx_w   = (const float*)d_in[18];
    const float* lnx_b   = (const float*)d_in[19];
    float* out = (float*)d_out;

    k1_ln<<<1, 1024>>>(x, state1, ln1_w, ln1_b, tmx, out);
    launch_pdl(k2_maa_down, dim3(128), dim3(320), maa_w1);
    launch_pdl(k3_maa_up, dim3(80), dim3(256), maa_w2, tmaa);
    launch_pdl(k4_gemv4, dim3(2064), dim3(256), Wr, Wk, Wv, Wg, dw1);
    launch_pdl(k5_heads, dim3(64), dim3(256), state2, dw2, tdec, tfirst, lnx_w, lnx_b, out);
    launch_pdl(k6_out, dim3(512), dim3(256), Wo, x, out);
}

// round 10
// speedup vs baseline: 1.2956x; 1.0098x over previous
#include <cuda_runtime.h>
#include <stdint.h>
#include <math.h>

#define H   4096
#define HS  64
#define NH  64
#define TM  64
#define TD  128
#define EPS 1e-5f
#define CHUNK 256              // floats per row-chunk (1KB/row-chunk)
#define NCH   (H / CHUNK)      // 16 chunks
#define NSTG  3

// ---------------- scratch ----------------
__device__ __align__(16) float g_xl[H];
__device__ __align__(16) float g_sx[H];
__device__ __align__(16) float g_xm[H];
__device__ __align__(16) float g_y320[5 * TM];
__device__ __align__(16) float g_mix[5 * H];
__device__ __align__(16) float g_r[H];
__device__ __align__(16) float g_k[H];
__device__ __align__(16) float g_v[H];
__device__ __align__(16) float g_g[H];
__device__ __align__(16) float g_z128[TD];
__device__ __align__(16) float g_og[H];

__device__ __forceinline__ uint32_t smem_u32(const void* p) {
    return (uint32_t)__cvta_generic_to_shared(p);
}
__device__ __forceinline__ void cp16(uint32_t d, const void* s) {
    asm volatile("cp.async.cg.shared.global [%0], [%1], 16;" :: "r"(d), "l"(s));
}
__device__ __forceinline__ void cp_commit() {
    asm volatile("cp.async.commit_group;" ::: "memory");
}
template <int N>
__device__ __forceinline__ void cp_wait() {
    asm volatile("cp.async.wait_group %0;" :: "n"(N) : "memory");
}

// ---------------- K1: LN(x), sx, xm, zero accumulators ----------------
__global__ void k1_ln(const float* __restrict__ x,
                      const float* __restrict__ state1,
                      const float* __restrict__ ln1w,
                      const float* __restrict__ ln1b,
                      const float* __restrict__ tmx,
                      float* __restrict__ out) {
    __shared__ float ssum[32], ssq[32];
    int tid = threadIdx.x;              // 1024 threads
    float vals[4];
    float s = 0.f, q = 0.f;
#pragma unroll
    for (int i = 0; i < 4; i++) {
        float v = x[tid + i * 1024];
        vals[i] = v; s += v; q += v * v;
    }
    for (int o = 16; o; o >>= 1) { s += __shfl_down_sync(~0u, s, o); q += __shfl_down_sync(~0u, q, o); }
    if ((tid & 31) == 0) { ssum[tid >> 5] = s; ssq[tid >> 5] = q; }
    __syncthreads();
    if (tid < 32) {
        float a = ssum[tid], b = ssq[tid];
        for (int o = 16; o; o >>= 1) { a += __shfl_down_sync(~0u, a, o); b += __shfl_down_sync(~0u, b, o); }
        if (tid == 0) { ssum[0] = a; ssq[0] = b; }
    }
    __syncthreads();
    float mu = ssum[0] * (1.f / H);
    float var = ssq[0] * (1.f / H) - mu * mu;
    float inv = rsqrtf(var + EPS);
#pragma unroll
    for (int i = 0; i < 4; i++) {
        int idx = tid + i * 1024;
        float xl = (vals[i] - mu) * inv * ln1w[idx] + ln1b[idx];
        g_xl[idx] = xl;
        out[H + idx] = xl;                       // output #2: xl
        float sx = state1[idx] - xl;
        g_sx[idx] = sx;
        g_xm[idx] = xl + sx * tmx[idx];
    }
    if (tid < 5 * TM) g_y320[tid] = 0.f;
    if (tid < TD)     g_z128[tid] = 0.f;
}

// ---------------- K2: y320 = xm @ maa_w1 (4096 x 320), 128 blocks ----------------
__global__ void k2_maa_down(const float* __restrict__ w1) {
    cudaGridDependencySynchronize();
    int t = threadIdx.x;                 // 320 threads
    int j0 = blockIdx.x * 32;            // 128 blocks x 32 rows
    float acc = 0.f;
#pragma unroll 8
    for (int j = j0; j < j0 + 32; j++)
        acc += g_xm[j] * w1[j * 320 + t];
    atomicAdd(&g_y320[t], acc);
}

// ---------------- K3: mixes = xl + sx*(lora_up + time_maa) ----------------
__global__ void k3_maa_up(const float* __restrict__ w2,
                          const float* __restrict__ tmaa) {
    cudaGridDependencySynchronize();
    int gid = blockIdx.x * 256 + threadIdx.x;   // 80 blocks * 256 = 5*4096
    int f = gid >> 12;
    int h = gid & (H - 1);
    __shared__ float ty[TM];
    if (threadIdx.x < TM) ty[threadIdx.x] = tanhf(g_y320[f * TM + threadIdx.x]);
    __syncthreads();
    const float* base = w2 + (size_t)f * TM * H + h;
    float acc = 0.f;
#pragma unroll
    for (int t = 0; t < TM; t++) acc += ty[t] * base[(size_t)t * H];
    g_mix[gid] = g_xl[h] + g_sx[h] * (acc + tmaa[gid]);
}

// ---------------- K4: 4 big GEMVs (per-warp barrier-free cp.async pipeline) ----------------
__global__ void __launch_bounds__(256) k4_gemv4(
        const float* __restrict__ Wr, const float* __restrict__ Wk,
        const float* __restrict__ Wv, const float* __restrict__ Wg,
        const float* __restrict__ dw1) {
    __shared__ float sv[H];                        // 16KB vector tile
    __shared__ float stage[NSTG][8][CHUNK];        // 3 x 8KB, per-warp slices
    __shared__ float sh[256];

    if (blockIdx.x >= 2048) {
        cudaGridDependencySynchronize();
        // decay stage 1: z128 = mw @ decay_w1 (4096 x 128), 16 blocks x 256 rows
        int bb = blockIdx.x - 2048;
        int j0 = bb * 256;
        int t = threadIdx.x & 127;
        int sub = threadIdx.x >> 7;
        float acc = 0.f;
        for (int j = j0 + sub; j < j0 + 256; j += 2)
            acc += g_mix[j] * dw1[j * TD + t];   // mw = mix[0]
        sh[threadIdx.x] = acc;
        __syncthreads();
        if (sub == 0) atomicAdd(&g_z128[t], sh[t] + sh[t + 128]);
        return;
    }

    int mat = blockIdx.x >> 9;                   // 512 blocks per matrix
    const float* W; const float* vec;
    if (mat == 0)      { W = Wr; vec = g_mix + 3 * H; }   // r <- mr
    else if (mat == 1) { W = Wk; vec = g_mix + 1 * H; }   // k <- mk
    else if (mat == 2) { W = Wv; vec = g_mix + 2 * H; }   // v <- mv
    else               { W = Wg; vec = g_mix + 4 * H; }   // g <- mg

    int tid = threadIdx.x;
    int warp = tid >> 5, lane = tid & 31;
    int row = (blockIdx.x & 511) * 8 + warp;
    const float* Wrow = W + (size_t)row * H;     // this warp's row

    // per-warp staging: lane copies float4 slots lane and lane+32 of each 64-float4 chunk
    uint32_t sdst[NSTG];
#pragma unroll
    for (int s = 0; s < NSTG; s++)
        sdst[s] = smem_u32(&stage[s][warp][0]) + lane * 16;

    // prologue: weights are input-independent — issue BEFORE the PDL sync
#pragma unroll
    for (int s = 0; s < NSTG; s++) {
        const float4* src = (const float4*)(Wrow + s * CHUNK);
        cp16(sdst[s],            src + lane);
        cp16(sdst[s] + 32 * 16,  src + lane + 32);
        cp_commit();
    }

    cudaGridDependencySynchronize();

    // stage the vector (depends on K3); one barrier total
    {
        const float4* V4 = (const float4*)vec;
        float4* S4 = (float4*)sv;
#pragma unroll
        for (int i = 0; i < 4; i++)
            S4[tid + i * 256] = V4[tid + i * 256];
    }
    __syncthreads();

    float acc = 0.f;
#pragma unroll
    for (int c = 0; c < NCH; c++) {
        if (c < NCH - 2)       cp_wait<NSTG - 1>();
        else if (c == NCH - 2) cp_wait<1>();
        else                   cp_wait<0>();
        // lane reads exactly the slots it issued — no barrier needed
        const float4* SB = (const float4*)&stage[c % NSTG][warp][0];
        const float4* SV = (const float4*)&sv[c * CHUNK];
        float4 w0 = SB[lane],      u0 = SV[lane];
        float4 w1_ = SB[lane + 32], u1 = SV[lane + 32];
        acc += w0.x * u0.x + w0.y * u0.y + w0.z * u0.z + w0.w * u0.w;
        acc += w1_.x * u1.x + w1_.y * u1.y + w1_.z * u1.z + w1_.w * u1.w;
        if (c + NSTG < NCH) {
            const float4* src = (const float4*)(Wrow + (c + NSTG) * CHUNK);
            cp16(sdst[c % NSTG],           src + lane);
            cp16(sdst[c % NSTG] + 32 * 16, src + lane + 32);
            cp_commit();
        }
    }

    for (int o = 16; o; o >>= 1) acc += __shfl_down_sync(~0u, acc, o);
    if (lane == 0) {
        if (mat == 0)      g_r[row] = acc;
        else if (mat == 1) g_k[row] = acc;
        else if (mat == 2) g_v[row] = acc;
        else               g_g[row] = acc / (1.f + expf(-acc)); // silu
    }
}

// ---------------- K5: per-head decay/wkv/state/norm (256 threads/head) ----------------
__global__ void k5_heads(const float* __restrict__ state2,
                         const float* __restrict__ dw2,
                         const float* __restrict__ tdec,
                         const float* __restrict__ tfirst,
                         const float* __restrict__ lnxw,
                         const float* __restrict__ lnxb,
                         float* __restrict__ out) {
    cudaGridDependencySynchronize();
    int h = blockIdx.x;                 // 64 heads
    int tid = threadIdx.x;              // 256 threads
    int j = tid & 63;                   // column within head
    int p = tid >> 6;                   // 0..3 partition
    const float* s2 = state2 + (size_t)h * HS * HS;

    __shared__ float tz[TD], sr[HS], sk[HS], std_[HS], red[HS];
    __shared__ float part[4][HS];

    if (tid < TD) tz[tid] = tanhf(g_z128[tid]);
    __syncthreads();

    int gi = h * HS + j;

    float dacc = 0.f;
#pragma unroll
    for (int t = p * 32; t < p * 32 + 32; t++)
        dacc += tz[t] * dw2[(size_t)t * H + gi];
    part[p][j] = dacc;
    __syncthreads();
    if (p == 0) {
        float d = part[0][j] + part[1][j] + part[2][j] + part[3][j] + tdec[gi];
        d = fminf(fmaxf(d, -9.72f), 2.27f);
        std_[j] = expf(-expf(d));
        float rs = g_r[gi], ks = g_k[gi];
        sr[j] = rs; sk[j] = ks;
        red[j] = rs * ks * tfirst[gi];
    }
    __syncthreads();

    float a = 0.f;
#pragma unroll
    for (int t = 0; t < HS; t++) a += red[t];   // broadcast reads

    float vs = g_v[gi];
    float* s2o = out + 2 * H + (size_t)h * HS * HS;   // output #3: state2_out
    float acc2 = 0.f;
#pragma unroll
    for (int i = p * 16; i < p * 16 + 16; i++) {
        float s2v = s2[i * HS + j];
        acc2 += sr[i] * s2v;
        s2o[i * HS + j] = sk[i] * vs + s2v * std_[i];
    }
    part[p][j] = acc2;
    __syncthreads();

    if (p == 0) {
        float oj = a * vs + part[0][j] + part[1][j] + part[2][j] + part[3][j];
        red[j] = oj;
    }
    __syncthreads();
    if (p == 0) {
        float s = 0.f, q = 0.f;
#pragma unroll
        for (int t = 0; t < HS; t++) { float u = red[t]; s += u; q += u * u; }
        float mu = s * (1.f / HS);
        float var = q * (1.f / HS) - mu * mu;
        float nj = (red[j] - mu) * rsqrtf(var + EPS);
        g_og[gi] = (nj * lnxw[gi] + lnxb[gi]) * g_g[gi];
    }
}

// ---------------- K6: out = x + og @ Wo.T (per-warp barrier-free pipeline) ----------------
__global__ void __launch_bounds__(256) k6_out(const float* __restrict__ Wo,
                                              const float* __restrict__ x,
                                              float* __restrict__ out) {
    __shared__ float sv[H];
    __shared__ float stage[NSTG][8][CHUNK];
    int tid = threadIdx.x;
    int warp = tid >> 5, lane = tid & 31;
    int row = blockIdx.x * 8 + warp;
    const float* Wrow = Wo + (size_t)row * H;

    uint32_t sdst[NSTG];
#pragma unroll
    for (int s = 0; s < NSTG; s++)
        sdst[s] = smem_u32(&stage[s][warp][0]) + lane * 16;

#pragma unroll
    for (int s = 0; s < NSTG; s++) {
        const float4* src = (const float4*)(Wrow + s * CHUNK);
        cp16(sdst[s],            src + lane);
        cp16(sdst[s] + 32 * 16,  src + lane + 32);
        cp_commit();
    }

    cudaGridDependencySynchronize();

    {
        const float4* V4 = (const float4*)g_og;
        float4* S4 = (float4*)sv;
#pragma unroll
        for (int i = 0; i < 4; i++)
            S4[tid + i * 256] = V4[tid + i * 256];
    }
    __syncthreads();

    float acc = 0.f;
#pragma unroll
    for (int c = 0; c < NCH; c++) {
        if (c < NCH - 2)       cp_wait<NSTG - 1>();
        else if (c == NCH - 2) cp_wait<1>();
        else                   cp_wait<0>();
        const float4* SB = (const float4*)&stage[c % NSTG][warp][0];
        const float4* SV = (const float4*)&sv[c * CHUNK];
        float4 w0 = SB[lane],       u0 = SV[lane];
        float4 w1_ = SB[lane + 32], u1 = SV[lane + 32];
        acc += w0.x * u0.x + w0.y * u0.y + w0.z * u0.z + w0.w * u0.w;
        acc += w1_.x * u1.x + w1_.y * u1.y + w1_.z * u1.z + w1_.w * u1.w;
        if (c + NSTG < NCH) {
            const float4* src = (const float4*)(Wrow + (c + NSTG) * CHUNK);
            cp16(sdst[c % NSTG],           src + lane);
            cp16(sdst[c % NSTG] + 32 * 16, src + lane + 32);
            cp_commit();
        }
    }

    for (int o = 16; o; o >>= 1) acc += __shfl_down_sync(~0u, acc, o);
    if (lane == 0) out[row] = x[row] + acc;
}

// ---------------- launch helpers ----------------
template <typename... Args>
static void launch_pdl(void (*kern)(Args...), dim3 grid, dim3 block, Args... args) {
    cudaLaunchConfig_t cfg = {};
    cfg.gridDim = grid;
    cfg.blockDim = block;
    cfg.dynamicSmemBytes = 0;
    cfg.stream = 0;
    cudaLaunchAttribute attr[1];
    attr[0].id = cudaLaunchAttributeProgrammaticStreamSerialization;
    attr[0].val.programmaticStreamSerializationAllowed = 1;
    cfg.attrs = attr;
    cfg.numAttrs = 1;
    cudaLaunchKernelEx(&cfg, kern, args...);
}

extern "C" void kernel_launch(void* const* d_in, const int* in_sizes, int n_in,
                              void* d_out, int out_size) {
    const float* x       = (const float*)d_in[0];
    const float* state1  = (const float*)d_in[1];
    const float* state2  = (const float*)d_in[2];
    const float* ln1_w   = (const float*)d_in[3];
    const float* ln1_b   = (const float*)d_in[4];
    const float* tmx     = (const float*)d_in[5];
    const float* tmaa    = (const float*)d_in[6];
    const float* maa_w1  = (const float*)d_in[7];
    const float* maa_w2  = (const float*)d_in[8];
    const float* tdec    = (const float*)d_in[9];
    const float* tfirst  = (const float*)d_in[10];
    const float* dw1     = (const float*)d_in[11];
    const float* dw2     = (const float*)d_in[12];
    const float* Wr      = (const float*)d_in[13];
    const float* Wk      = (const float*)d_in[14];
    const float* Wv      = (const float*)d_in[15];
    const float* Wg      = (const float*)d_in[16];
    const float* Wo      = (const float*)d_in[17];
    const float* lnx_w   = (const float*)d_in[18];
    const float* lnx_b   = (const float*)d_in[19];
    float* out = (float*)d_out;

    k1_ln<<<1, 1024>>>(x, state1, ln1_w, ln1_b, tmx, out);
    launch_pdl(k2_maa_down, dim3(128), dim3(320), maa_w1);
    launch_pdl(k3_maa_up, dim3(80), dim3(256), maa_w2, tmaa);
    launch_pdl(k4_gemv4, dim3(2064), dim3(256), Wr, Wk, Wv, Wg, dw1);
    launch_pdl(k5_heads, dim3(64), dim3(256), state2, dw2, tdec, tfirst, lnx_w, lnx_b, out);
    launch_pdl(k6_out, dim3(512), dim3(256), Wo, x, out);
}